// round 14
// baseline (speedup 1.0000x reference)
#include <cuda_runtime.h>
#include <math.h>
#include <stdint.h>

typedef unsigned long long u64;
typedef unsigned int u32;

// ---------------- problem constants ----------------
#define BB   4
#define NNC  6
#define CINC 512
#define CTC  64
#define FHC  16
#define FWC  44
#define DDC  41
#define PPI  (FHC*FWC)          // 704
#define NIMG (BB*NNC)           // 24
#define NPIX (NIMG*PPI)         // 16896
#define MPAD 112                // [0,41) depth logits, [48,112) cvt (aligned)
#define CVT0 48
#define NXXC 128
#define NYYC 128
#define NVOX (BB*NYYC*NXXC)     // 65536
#define NCOL (NIMG*FWC)         // 1056 (img, w) columns

#define XS_LD 72
#define WS_LD 132
#define GEMM_SMEM ((2*32*XS_LD + 2*32*WS_LD) * 4)   // 52224 bytes

// ---------------- scratch ----------------
__device__ __align__(16) float g_WdTp[512*128];     // [k][q*16+j], tf32-rounded, o=8j+q
__device__ __align__(16) float g_bias[112];
__device__ __align__(16) float g_mats[NIMG*24];
__device__ __align__(16) float g_feat[NPIX*MPAD];

// ---------------- helpers ----------------
__device__ __forceinline__ void cpa16(uint32_t s, const void* g)
{
    asm volatile("cp.async.cg.shared.global [%0], [%1], 16;" :: "r"(s), "l"(g));
}
#define CP_COMMIT() asm volatile("cp.async.commit_group;")
#define CP_WAIT1()  asm volatile("cp.async.wait_group 1;")
#define CP_WAIT0()  asm volatile("cp.async.wait_group 0;")

__device__ __forceinline__ u32 f2tf32(float x)
{
    u32 r;
    asm("cvt.rna.tf32.f32 %0, %1;" : "=r"(r) : "f"(x));
    return r;
}

__device__ __forceinline__ void inv3(const float* a, float* r)
{
    float det = a[0]*(a[4]*a[8]-a[5]*a[7])
              - a[1]*(a[3]*a[8]-a[5]*a[6])
              + a[2]*(a[3]*a[7]-a[4]*a[6]);
    float id = 1.0f / det;
    r[0] = (a[4]*a[8]-a[5]*a[7])*id;
    r[1] = (a[2]*a[7]-a[1]*a[8])*id;
    r[2] = (a[1]*a[5]-a[2]*a[4])*id;
    r[3] = (a[5]*a[6]-a[3]*a[8])*id;
    r[4] = (a[0]*a[8]-a[2]*a[6])*id;
    r[5] = (a[2]*a[3]-a[0]*a[5])*id;
    r[6] = (a[3]*a[7]-a[4]*a[6])*id;
    r[7] = (a[1]*a[6]-a[0]*a[7])*id;
    r[8] = (a[0]*a[4]-a[1]*a[3])*id;
}

// ---------------- prep: zero OUT, WdTp (tf32, permuted), per-image mats -----------
__global__ void k_prep(float* __restrict__ out,
                       const float* __restrict__ Wd, const float* __restrict__ bd,
                       const float* __restrict__ rots, const float* __restrict__ trans,
                       const float* __restrict__ intrins, const float* __restrict__ post_rots,
                       const float* __restrict__ post_trans)
{
    int bi = blockIdx.x;
    int tid = threadIdx.x;
    if (bi < 4096) {                               // zero out: 4096*256 float4 = 16.8MB
        reinterpret_cast<float4*>(out)[bi * 256 + tid] = make_float4(0.f,0.f,0.f,0.f);
    } else if (bi < 4352) {                        // WdTp: 256*256 = 65536
        int idx = (bi - 4096) * 256 + tid;
        int k = idx >> 7, col = idx & 127;
        int q = col >> 4, jj = col & 15;
        int o = 8 * jj + q;
        float v = 0.f;
        if (jj < 14 && o < 105)
            v = __uint_as_float(f2tf32(Wd[o * 512 + k]));
        g_WdTp[idx] = v;
        if (idx < 112) g_bias[idx] = (idx < 105) ? bd[idx] : 0.f;
    } else {                                       // mats
        int bn = tid;
        if (bn >= NIMG) return;
        float P[9], Pi[9], K[9], Ki[9], R[9], C[9];
        #pragma unroll
        for (int i = 0; i < 9; i++) {
            P[i] = post_rots[bn*9 + i];
            K[i] = intrins[bn*9 + i];
            R[i] = rots[bn*9 + i];
        }
        inv3(P, Pi);
        inv3(K, Ki);
        #pragma unroll
        for (int i = 0; i < 3; i++)
            #pragma unroll
            for (int j = 0; j < 3; j++)
                C[i*3+j] = R[i*3+0]*Ki[0*3+j] + R[i*3+1]*Ki[1*3+j] + R[i*3+2]*Ki[2*3+j];
        float* m = &g_mats[bn*24];
        #pragma unroll
        for (int i = 0; i < 9; i++) { m[i] = Pi[i]; m[9+i] = C[i]; }
        #pragma unroll
        for (int i = 0; i < 3; i++) { m[18+i] = trans[bn*3+i]; m[21+i] = post_trans[bn*3+i]; }
    }
}

// ---------------- GEMM (tf32 mma.sync) — byte-identical to round-13 pass ----------
__global__ __launch_bounds__(128) void k_gemm(const float* __restrict__ x)
{
    extern __shared__ float smem[];
    float* Xs = smem;                       // [2][32][XS_LD]
    float* Ws = smem + 2*32*XS_LD;          // [2][32][WS_LD]

    int img = blockIdx.x / 11;
    int p0  = (blockIdx.x % 11) * 64;
    const float* Ximg = x + (size_t)img * CINC * PPI;

    int tid = threadIdx.x;
    int w   = tid >> 5;
    int lid = tid & 31;
    int qa  = lid >> 2;
    int ca  = lid & 3;

    uint32_t sX = (uint32_t)__cvta_generic_to_shared(Xs);
    uint32_t sW = (uint32_t)__cvta_generic_to_shared(Ws);

    float acc[14][4];
    #pragma unroll
    for (int j = 0; j < 14; j++)
        #pragma unroll
        for (int i = 0; i < 4; i++) acc[j][i] = 0.f;

    #pragma unroll
    for (int t = 0; t < 4; t++) {
        int i = tid + t * 128;
        int row = i >> 4, colv = i & 15;
        cpa16(sX + (uint32_t)((row * XS_LD + colv * 4) * 4),
              &Ximg[(size_t)row * PPI + p0 + colv * 4]);
    }
    #pragma unroll
    for (int t = 0; t < 8; t++) {
        int i = tid + t * 128;
        int row = i >> 5, colv = i & 31;
        cpa16(sW + (uint32_t)((row * WS_LD + colv * 4) * 4),
              &g_WdTp[row * 128 + colv * 4]);
    }
    CP_COMMIT();

    for (int c = 0; c < 16; c++) {
        int buf = c & 1;
        if (c < 15) {
            int nb = (c + 1) & 1;
            int k0 = (c + 1) * 32;
            #pragma unroll
            for (int t = 0; t < 4; t++) {
                int i = tid + t * 128;
                int row = i >> 4, colv = i & 15;
                cpa16(sX + (uint32_t)(((nb*32 + row) * XS_LD + colv * 4) * 4),
                      &Ximg[(size_t)(k0 + row) * PPI + p0 + colv * 4]);
            }
            #pragma unroll
            for (int t = 0; t < 8; t++) {
                int i = tid + t * 128;
                int row = i >> 5, colv = i & 31;
                cpa16(sW + (uint32_t)(((nb*32 + row) * WS_LD + colv * 4) * 4),
                      &g_WdTp[(k0 + row) * 128 + colv * 4]);
            }
            CP_COMMIT();
            CP_WAIT1();
        } else {
            CP_WAIT0();
        }
        __syncthreads();

        const float* Xb = &Xs[buf * 32 * XS_LD];
        const float* Wb = &Ws[buf * 32 * WS_LD];

        #pragma unroll
        for (int s = 0; s < 4; s++) {
            const float* xa = &Xb[(s*8 + ca) * XS_LD + 16*w + qa];
            u32 a0 = f2tf32(xa[0]);
            u32 a1 = f2tf32(xa[8]);
            u32 a2 = f2tf32(xa[4*XS_LD]);
            u32 a3 = f2tf32(xa[4*XS_LD + 8]);
            const uint4* wr0 = reinterpret_cast<const uint4*>(&Wb[(s*8 + ca) * WS_LD + qa*16]);
            const uint4* wr1 = reinterpret_cast<const uint4*>(&Wb[(s*8 + ca + 4) * WS_LD + qa*16]);
            u32 b0a[16], b1a[16];
            #pragma unroll
            for (int v = 0; v < 4; v++) {
                uint4 t0 = wr0[v], t1 = wr1[v];
                b0a[v*4+0]=t0.x; b0a[v*4+1]=t0.y; b0a[v*4+2]=t0.z; b0a[v*4+3]=t0.w;
                b1a[v*4+0]=t1.x; b1a[v*4+1]=t1.y; b1a[v*4+2]=t1.z; b1a[v*4+3]=t1.w;
            }
            #pragma unroll
            for (int j = 0; j < 14; j++) {
                asm volatile(
                    "mma.sync.aligned.m16n8k8.row.col.f32.tf32.tf32.f32 "
                    "{%0,%1,%2,%3}, {%4,%5,%6,%7}, {%8,%9}, {%0,%1,%2,%3};"
                    : "+f"(acc[j][0]), "+f"(acc[j][1]), "+f"(acc[j][2]), "+f"(acc[j][3])
                    : "r"(a0), "r"(a1), "r"(a2), "r"(a3), "r"(b0a[j]), "r"(b1a[j]));
            }
        }
        __syncthreads();
    }

    // epilogue: logits at [0,41), cvt at [48,112); pad o >= 105 skipped
    {
        int p = img * PPI + p0 + 16*w + qa;
        #pragma unroll
        for (int j = 0; j < 14; j++) {
            int o = 8*j + 2*ca;
            if (o < 105) {
                int o0 = (o < DDC) ? o : o + 7;
                float b0 = g_bias[o];
                g_feat[(size_t)p * MPAD + o0]     = acc[j][0] + b0;
                g_feat[(size_t)(p+8) * MPAD + o0] = acc[j][2] + b0;
            }
            if (o + 1 < 105) {
                int o1 = (o + 1 < DDC) ? o + 1 : o + 8;
                float b1 = g_bias[o + 1];
                g_feat[(size_t)p * MPAD + o1]     = acc[j][1] + b1;
                g_feat[(size_t)(p+8) * MPAD + o1] = acc[j][3] + b1;
            }
        }
    }
}

// ---------------- column kernel: softmax + geometry + D = dep^T @ cvt + scatter ---
// one block = one (img, w) column; scatter DIRECTLY into out [b][c][y][x].
__global__ __launch_bounds__(256) void k_col(float* __restrict__ out)
{
    __shared__ float s_log[FHC][DDC + 1];    // logits -> dep (in place)
    __shared__ float s_cvt[FHC][CTC];        // [h][c]
    __shared__ int   s_km[DDC];              // kept-h bitmask per d
    __shared__ int   s_vox[DDC];             // voxel per d (or -1)

    int col = blockIdx.x;
    int img = col / FWC;
    int w   = col - img * FWC;
    int tid = threadIdx.x;
    int wid = tid >> 5;
    int l   = tid & 31;

    // ---- phase 1: load logits + cvt; init masks ----
    if (tid < DDC) s_km[tid] = 0;
    for (int i = tid; i < FHC * DDC; i += 256) {
        int h = i / DDC, d = i - h * DDC;
        s_log[h][d] = g_feat[(size_t)(img * PPI + h * FWC + w) * MPAD + d];
    }
    {
        int h = tid >> 4, c4 = tid & 15;     // 256 = 16h * 16 float4
        float4 v = *reinterpret_cast<const float4*>(
            &g_feat[(size_t)(img * PPI + h * FWC + w) * MPAD + CVT0 + c4 * 4]);
        *reinterpret_cast<float4*>(&s_cvt[h][c4 * 4]) = v;
    }
    __syncthreads();

    // ---- phase 2a: softmax (warp wid -> pixels 2*wid, 2*wid+1), in place ----
    #pragma unroll
    for (int t = 0; t < 2; t++) {
        int h = wid * 2 + t;
        float f0 = s_log[h][l];
        float f1 = (l < 9) ? s_log[h][32 + l] : -INFINITY;
        float m = fmaxf(f0, f1);
        #pragma unroll
        for (int o = 16; o; o >>= 1) m = fmaxf(m, __shfl_xor_sync(0xFFFFFFFFu, m, o));
        float e0 = __expf(f0 - m);
        float e1 = (l < 9) ? __expf(f1 - m) : 0.f;
        float s = e0 + e1;
        #pragma unroll
        for (int o = 16; o; o >>= 1) s += __shfl_xor_sync(0xFFFFFFFFu, s, o);
        float inv = 1.0f / s;
        s_log[h][l] = e0 * inv;
        if (l < 9) s_log[h][32 + l] = e1 * inv;
    }

    // ---- phase 2b: geometry over 656 (d,h) pairs (expressions verbatim) ----
    {
        const float* mm = &g_mats[img * 24];
        const float offx = -50.8f - 0.4f;
        const float offz = 0.0f - 10.0f;
        float xs = (float)((double)w * (703.0 / 43.0));
        for (int i = tid; i < DDC * FHC; i += 256) {
            int d = i >> 4, h = i & 15;
            float ys = (float)h * 17.0f;
            float ax = xs - mm[21], ay = ys - mm[22];
            float qb0 = mm[0]*ax + mm[1]*ay;
            float qb1 = mm[3]*ax + mm[4]*ay;
            float qb2 = mm[6]*ax + mm[7]*ay;
            float az = (4.0f + (float)d) - mm[23];
            float q0 = qb0 + mm[2]*az;
            float q1 = qb1 + mm[5]*az;
            float q2 = qb2 + mm[8]*az;
            float r0 = q0 * q2, r1 = q1 * q2, r2 = q2;
            float wx = mm[9]*r0  + mm[10]*r1 + mm[11]*r2 + mm[18];
            float wy = mm[12]*r0 + mm[13]*r1 + mm[14]*r2 + mm[19];
            float wz = mm[15]*r0 + mm[16]*r1 + mm[17]*r2 + mm[20];
            int gx = (int)((wx - offx) / 0.8f);
            int gy = (int)((wy - offx) / 0.8f);
            int gz = (int)((wz - offz) / 20.0f);
            bool inxy = (gx >= 0 && gx < NXXC && gy >= 0 && gy < NYYC);
            if (inxy && gz == 0) atomicOr(&s_km[d], 1 << h);
            if (h == 0) {
                int b = img / NNC;
                s_vox[d] = inxy ? ((b * NYYC + gy) * NXXC + gx) : -1;
            }
        }
    }
    __syncthreads();

    // ---- phase 3: D[d][2l..2l+1] = sum_h dep[h][d] * cvt[h][2l..]; scatter ----
    float2 acc[6];
    int    dk[6];
    int    kmv[6];
    #pragma unroll
    for (int k = 0; k < 6; k++) {
        acc[k] = make_float2(0.f, 0.f);
        dk[k] = wid + 8 * k;
        kmv[k] = (dk[k] < DDC) ? s_km[dk[k]] : 0;
    }

    #pragma unroll
    for (int h = 0; h < FHC; h++) {
        float2 cv = *reinterpret_cast<float2*>(&s_cvt[h][2 * l]);
        #pragma unroll
        for (int k = 0; k < 6; k++) {
            if ((kmv[k] >> h) & 1) {
                float dep = s_log[h][dk[k]];
                acc[k].x = fmaf(dep, cv.x, acc[k].x);
                acc[k].y = fmaf(dep, cv.y, acc[k].y);
            }
        }
    }

    // flush directly into out[b][c][y][x]:
    //   vox = b*16384 + y*128 + x ;  idx = b*2^20 + c*16384 + (y*128+x), c = 2l, 2l+1
    #pragma unroll
    for (int k = 0; k < 6; k++) {
        if (kmv[k] != 0) {
            int vox = s_vox[dk[k]];
            if (vox >= 0) {
                int b  = vox >> 14;
                int yx = vox & 16383;
                float* dst = out + ((size_t)b << 20) + ((size_t)l << 15) + yx;
                asm volatile("red.global.add.f32 [%0], %1;"
                             :: "l"(dst), "f"(acc[k].x) : "memory");
                asm volatile("red.global.add.f32 [%0], %1;"
                             :: "l"(dst + 16384), "f"(acc[k].y) : "memory");
            }
        }
    }
}

// ---------------- launch ----------------
extern "C" void kernel_launch(void* const* d_in, const int* in_sizes, int n_in,
                              void* d_out, int out_size)
{
    const float* x          = (const float*)d_in[0];
    const float* rots       = (const float*)d_in[1];
    const float* trans      = (const float*)d_in[2];
    const float* intrins    = (const float*)d_in[3];
    const float* post_rots  = (const float*)d_in[4];
    const float* post_trans = (const float*)d_in[5];
    const float* Wd         = (const float*)d_in[6];
    const float* bd         = (const float*)d_in[7];
    float* out = (float*)d_out;

    cudaFuncSetAttribute(k_gemm, cudaFuncAttributeMaxDynamicSharedMemorySize, GEMM_SMEM);

    k_prep<<<4353, 256>>>(out, Wd, bd, rots, trans, intrins, post_rots, post_trans);
    k_gemm<<<NIMG * 11, 128, GEMM_SMEM>>>(x);
    k_col<<<NCOL, 256>>>(out);
}

// round 15
// speedup vs baseline: 1.1741x; 1.1741x over previous
#include <cuda_runtime.h>
#include <math.h>
#include <stdint.h>

typedef unsigned long long u64;
typedef unsigned int u32;

// ---------------- problem constants ----------------
#define BB   4
#define NNC  6
#define CINC 512
#define CTC  64
#define FHC  16
#define FWC  44
#define DDC  41
#define PPI  (FHC*FWC)          // 704
#define NIMG (BB*NNC)           // 24
#define NPIX (NIMG*PPI)         // 16896
#define MPAD 112                // [0,41) depth logits, [48,112) cvt (aligned)
#define CVT0 48
#define NXXC 128
#define NYYC 128
#define NVOX (BB*NYYC*NXXC)     // 65536
#define NCOL (NIMG*FWC)         // 1056 (img, w) columns

#define XS_LD 72
#define WS_LD 132
#define GEMM_SMEM ((2*32*XS_LD + 2*32*WS_LD) * 4)   // 52224 bytes

// ---------------- scratch ----------------
__device__ __align__(16) float g_WdTp[512*128];     // [k][q*16+j], tf32-rounded, o=8j+q
__device__ __align__(16) float g_bias[112];
__device__ __align__(16) float g_mats[NIMG*24];
__device__ __align__(16) float g_feat[NPIX*MPAD];
__device__ __align__(16) float g_bev[NVOX*CTC];     // [vox][c]

// ---------------- helpers ----------------
__device__ __forceinline__ void cpa16(uint32_t s, const void* g)
{
    asm volatile("cp.async.cg.shared.global [%0], [%1], 16;" :: "r"(s), "l"(g));
}
#define CP_COMMIT() asm volatile("cp.async.commit_group;")
#define CP_WAIT1()  asm volatile("cp.async.wait_group 1;")
#define CP_WAIT0()  asm volatile("cp.async.wait_group 0;")

__device__ __forceinline__ u32 f2tf32(float x)
{
    u32 r;
    asm("cvt.rna.tf32.f32 %0, %1;" : "=r"(r) : "f"(x));
    return r;
}

__device__ __forceinline__ void inv3(const float* a, float* r)
{
    float det = a[0]*(a[4]*a[8]-a[5]*a[7])
              - a[1]*(a[3]*a[8]-a[5]*a[6])
              + a[2]*(a[3]*a[7]-a[4]*a[6]);
    float id = 1.0f / det;
    r[0] = (a[4]*a[8]-a[5]*a[7])*id;
    r[1] = (a[2]*a[7]-a[1]*a[8])*id;
    r[2] = (a[1]*a[5]-a[2]*a[4])*id;
    r[3] = (a[5]*a[6]-a[3]*a[8])*id;
    r[4] = (a[0]*a[8]-a[2]*a[6])*id;
    r[5] = (a[2]*a[3]-a[0]*a[5])*id;
    r[6] = (a[3]*a[7]-a[4]*a[6])*id;
    r[7] = (a[1]*a[6]-a[0]*a[7])*id;
    r[8] = (a[0]*a[4]-a[1]*a[3])*id;
}

// ---------------- prep: zero bev (grid-stride x4), WdTp, per-image mats -----------
__global__ void k_prep(const float* __restrict__ Wd, const float* __restrict__ bd,
                       const float* __restrict__ rots, const float* __restrict__ trans,
                       const float* __restrict__ intrins, const float* __restrict__ post_rots,
                       const float* __restrict__ post_trans)
{
    int bi = blockIdx.x;
    int tid = threadIdx.x;
    if (bi < 1024) {                               // zero bev: 1024 blk * 256 thr * 4 float4
        float4* dst = reinterpret_cast<float4*>(g_bev);
        int base = bi * 1024 + tid;
        #pragma unroll
        for (int r = 0; r < 4; r++)
            dst[base + r * 256] = make_float4(0.f, 0.f, 0.f, 0.f);
    } else if (bi < 1280) {                        // WdTp: 256*256 = 65536
        int idx = (bi - 1024) * 256 + tid;
        int k = idx >> 7, col = idx & 127;
        int q = col >> 4, jj = col & 15;
        int o = 8 * jj + q;
        float v = 0.f;
        if (jj < 14 && o < 105)
            v = __uint_as_float(f2tf32(Wd[o * 512 + k]));
        g_WdTp[idx] = v;
        if (idx < 112) g_bias[idx] = (idx < 105) ? bd[idx] : 0.f;
    } else {                                       // mats
        int bn = tid;
        if (bn >= NIMG) return;
        float P[9], Pi[9], K[9], Ki[9], R[9], C[9];
        #pragma unroll
        for (int i = 0; i < 9; i++) {
            P[i] = post_rots[bn*9 + i];
            K[i] = intrins[bn*9 + i];
            R[i] = rots[bn*9 + i];
        }
        inv3(P, Pi);
        inv3(K, Ki);
        #pragma unroll
        for (int i = 0; i < 3; i++)
            #pragma unroll
            for (int j = 0; j < 3; j++)
                C[i*3+j] = R[i*3+0]*Ki[0*3+j] + R[i*3+1]*Ki[1*3+j] + R[i*3+2]*Ki[2*3+j];
        float* m = &g_mats[bn*24];
        #pragma unroll
        for (int i = 0; i < 9; i++) { m[i] = Pi[i]; m[9+i] = C[i]; }
        #pragma unroll
        for (int i = 0; i < 3; i++) { m[18+i] = trans[bn*3+i]; m[21+i] = post_trans[bn*3+i]; }
    }
}

// ---------------- GEMM (tf32 mma.sync) — byte-identical to round-13 pass ----------
__global__ __launch_bounds__(128) void k_gemm(const float* __restrict__ x)
{
    extern __shared__ float smem[];
    float* Xs = smem;                       // [2][32][XS_LD]
    float* Ws = smem + 2*32*XS_LD;          // [2][32][WS_LD]

    int img = blockIdx.x / 11;
    int p0  = (blockIdx.x % 11) * 64;
    const float* Ximg = x + (size_t)img * CINC * PPI;

    int tid = threadIdx.x;
    int w   = tid >> 5;
    int lid = tid & 31;
    int qa  = lid >> 2;
    int ca  = lid & 3;

    uint32_t sX = (uint32_t)__cvta_generic_to_shared(Xs);
    uint32_t sW = (uint32_t)__cvta_generic_to_shared(Ws);

    float acc[14][4];
    #pragma unroll
    for (int j = 0; j < 14; j++)
        #pragma unroll
        for (int i = 0; i < 4; i++) acc[j][i] = 0.f;

    #pragma unroll
    for (int t = 0; t < 4; t++) {
        int i = tid + t * 128;
        int row = i >> 4, colv = i & 15;
        cpa16(sX + (uint32_t)((row * XS_LD + colv * 4) * 4),
              &Ximg[(size_t)row * PPI + p0 + colv * 4]);
    }
    #pragma unroll
    for (int t = 0; t < 8; t++) {
        int i = tid + t * 128;
        int row = i >> 5, colv = i & 31;
        cpa16(sW + (uint32_t)((row * WS_LD + colv * 4) * 4),
              &g_WdTp[row * 128 + colv * 4]);
    }
    CP_COMMIT();

    for (int c = 0; c < 16; c++) {
        int buf = c & 1;
        if (c < 15) {
            int nb = (c + 1) & 1;
            int k0 = (c + 1) * 32;
            #pragma unroll
            for (int t = 0; t < 4; t++) {
                int i = tid + t * 128;
                int row = i >> 4, colv = i & 15;
                cpa16(sX + (uint32_t)(((nb*32 + row) * XS_LD + colv * 4) * 4),
                      &Ximg[(size_t)(k0 + row) * PPI + p0 + colv * 4]);
            }
            #pragma unroll
            for (int t = 0; t < 8; t++) {
                int i = tid + t * 128;
                int row = i >> 5, colv = i & 31;
                cpa16(sW + (uint32_t)(((nb*32 + row) * WS_LD + colv * 4) * 4),
                      &g_WdTp[(k0 + row) * 128 + colv * 4]);
            }
            CP_COMMIT();
            CP_WAIT1();
        } else {
            CP_WAIT0();
        }
        __syncthreads();

        const float* Xb = &Xs[buf * 32 * XS_LD];
        const float* Wb = &Ws[buf * 32 * WS_LD];

        #pragma unroll
        for (int s = 0; s < 4; s++) {
            const float* xa = &Xb[(s*8 + ca) * XS_LD + 16*w + qa];
            u32 a0 = f2tf32(xa[0]);
            u32 a1 = f2tf32(xa[8]);
            u32 a2 = f2tf32(xa[4*XS_LD]);
            u32 a3 = f2tf32(xa[4*XS_LD + 8]);
            const uint4* wr0 = reinterpret_cast<const uint4*>(&Wb[(s*8 + ca) * WS_LD + qa*16]);
            const uint4* wr1 = reinterpret_cast<const uint4*>(&Wb[(s*8 + ca + 4) * WS_LD + qa*16]);
            u32 b0a[16], b1a[16];
            #pragma unroll
            for (int v = 0; v < 4; v++) {
                uint4 t0 = wr0[v], t1 = wr1[v];
                b0a[v*4+0]=t0.x; b0a[v*4+1]=t0.y; b0a[v*4+2]=t0.z; b0a[v*4+3]=t0.w;
                b1a[v*4+0]=t1.x; b1a[v*4+1]=t1.y; b1a[v*4+2]=t1.z; b1a[v*4+3]=t1.w;
            }
            #pragma unroll
            for (int j = 0; j < 14; j++) {
                asm volatile(
                    "mma.sync.aligned.m16n8k8.row.col.f32.tf32.tf32.f32 "
                    "{%0,%1,%2,%3}, {%4,%5,%6,%7}, {%8,%9}, {%0,%1,%2,%3};"
                    : "+f"(acc[j][0]), "+f"(acc[j][1]), "+f"(acc[j][2]), "+f"(acc[j][3])
                    : "r"(a0), "r"(a1), "r"(a2), "r"(a3), "r"(b0a[j]), "r"(b1a[j]));
            }
        }
        __syncthreads();
    }

    // epilogue: logits at [0,41), cvt at [48,112); pad o >= 105 skipped
    {
        int p = img * PPI + p0 + 16*w + qa;
        #pragma unroll
        for (int j = 0; j < 14; j++) {
            int o = 8*j + 2*ca;
            if (o < 105) {
                int o0 = (o < DDC) ? o : o + 7;
                float b0 = g_bias[o];
                g_feat[(size_t)p * MPAD + o0]     = acc[j][0] + b0;
                g_feat[(size_t)(p+8) * MPAD + o0] = acc[j][2] + b0;
            }
            if (o + 1 < 105) {
                int o1 = (o + 1 < DDC) ? o + 1 : o + 8;
                float b1 = g_bias[o + 1];
                g_feat[(size_t)p * MPAD + o1]     = acc[j][1] + b1;
                g_feat[(size_t)(p+8) * MPAD + o1] = acc[j][3] + b1;
            }
        }
    }
}

// ---------------- column kernel: softmax + geometry + D = dep^T @ cvt + scatter ---
// one block = one (img, w) column; 256 threads = 8 warps. (round-13 pass, verbatim)
__global__ __launch_bounds__(256) void k_col()
{
    __shared__ float s_log[FHC][DDC + 1];    // logits -> dep (in place)
    __shared__ float s_cvt[FHC][CTC];        // [h][c]
    __shared__ int   s_km[DDC];              // kept-h bitmask per d
    __shared__ int   s_vox[DDC];             // voxel per d (or -1)

    int col = blockIdx.x;
    int img = col / FWC;
    int w   = col - img * FWC;
    int tid = threadIdx.x;
    int wid = tid >> 5;
    int l   = tid & 31;

    // ---- phase 1: load logits + cvt; init masks ----
    if (tid < DDC) s_km[tid] = 0;
    for (int i = tid; i < FHC * DDC; i += 256) {
        int h = i / DDC, d = i - h * DDC;
        s_log[h][d] = g_feat[(size_t)(img * PPI + h * FWC + w) * MPAD + d];
    }
    {
        int h = tid >> 4, c4 = tid & 15;     // 256 = 16h * 16 float4
        float4 v = *reinterpret_cast<const float4*>(
            &g_feat[(size_t)(img * PPI + h * FWC + w) * MPAD + CVT0 + c4 * 4]);
        *reinterpret_cast<float4*>(&s_cvt[h][c4 * 4]) = v;
    }
    __syncthreads();

    // ---- phase 2a: softmax (warp wid -> pixels 2*wid, 2*wid+1), in place ----
    #pragma unroll
    for (int t = 0; t < 2; t++) {
        int h = wid * 2 + t;
        float f0 = s_log[h][l];
        float f1 = (l < 9) ? s_log[h][32 + l] : -INFINITY;
        float m = fmaxf(f0, f1);
        #pragma unroll
        for (int o = 16; o; o >>= 1) m = fmaxf(m, __shfl_xor_sync(0xFFFFFFFFu, m, o));
        float e0 = __expf(f0 - m);
        float e1 = (l < 9) ? __expf(f1 - m) : 0.f;
        float s = e0 + e1;
        #pragma unroll
        for (int o = 16; o; o >>= 1) s += __shfl_xor_sync(0xFFFFFFFFu, s, o);
        float inv = 1.0f / s;
        s_log[h][l] = e0 * inv;
        if (l < 9) s_log[h][32 + l] = e1 * inv;
    }

    // ---- phase 2b: geometry over 656 (d,h) pairs (expressions verbatim) ----
    {
        const float* mm = &g_mats[img * 24];
        const float offx = -50.8f - 0.4f;
        const float offz = 0.0f - 10.0f;
        float xs = (float)((double)w * (703.0 / 43.0));
        for (int i = tid; i < DDC * FHC; i += 256) {
            int d = i >> 4, h = i & 15;
            float ys = (float)h * 17.0f;
            float ax = xs - mm[21], ay = ys - mm[22];
            float qb0 = mm[0]*ax + mm[1]*ay;
            float qb1 = mm[3]*ax + mm[4]*ay;
            float qb2 = mm[6]*ax + mm[7]*ay;
            float az = (4.0f + (float)d) - mm[23];
            float q0 = qb0 + mm[2]*az;
            float q1 = qb1 + mm[5]*az;
            float q2 = qb2 + mm[8]*az;
            float r0 = q0 * q2, r1 = q1 * q2, r2 = q2;
            float wx = mm[9]*r0  + mm[10]*r1 + mm[11]*r2 + mm[18];
            float wy = mm[12]*r0 + mm[13]*r1 + mm[14]*r2 + mm[19];
            float wz = mm[15]*r0 + mm[16]*r1 + mm[17]*r2 + mm[20];
            int gx = (int)((wx - offx) / 0.8f);
            int gy = (int)((wy - offx) / 0.8f);
            int gz = (int)((wz - offz) / 20.0f);
            bool inxy = (gx >= 0 && gx < NXXC && gy >= 0 && gy < NYYC);
            if (inxy && gz == 0) atomicOr(&s_km[d], 1 << h);
            if (h == 0) {
                int b = img / NNC;
                s_vox[d] = inxy ? ((b * NYYC + gy) * NXXC + gx) : -1;
            }
        }
    }
    __syncthreads();

    // ---- phase 3: D[d][2l..2l+1] = sum_h dep[h][d] * cvt[h][2l..]; scatter ----
    float2 acc[6];
    int    dk[6];
    int    kmv[6];
    #pragma unroll
    for (int k = 0; k < 6; k++) {
        acc[k] = make_float2(0.f, 0.f);
        dk[k] = wid + 8 * k;
        kmv[k] = (dk[k] < DDC) ? s_km[dk[k]] : 0;
    }

    #pragma unroll
    for (int h = 0; h < FHC; h++) {
        float2 cv = *reinterpret_cast<float2*>(&s_cvt[h][2 * l]);
        #pragma unroll
        for (int k = 0; k < 6; k++) {
            if ((kmv[k] >> h) & 1) {
                float dep = s_log[h][dk[k]];
                acc[k].x = fmaf(dep, cv.x, acc[k].x);
                acc[k].y = fmaf(dep, cv.y, acc[k].y);
            }
        }
    }

    #pragma unroll
    for (int k = 0; k < 6; k++) {
        if (kmv[k] != 0) {
            int vox = s_vox[dk[k]];
            if (vox >= 0) {
                float* dst = &g_bev[(size_t)vox * CTC + 2 * l];
                asm volatile("red.global.add.v2.f32 [%0], {%1, %2};"
                             :: "l"(dst), "f"(acc[k].x), "f"(acc[k].y) : "memory");
            }
        }
    }
}

// ---------------- transpose [vox][c] -> out [b][c][y][x]  (32x x 64c per block) ----
__global__ __launch_bounds__(256) void k_transpose(float* __restrict__ out)
{
    __shared__ float t[64][33];
    int x0 = blockIdx.x * 32;            // 4
    int by = blockIdx.y;                 // b*128 + y  (512)
    int b  = by >> 7, y = by & 127;
    int tid = threadIdx.x;               // 0..255

    // load: 32x * 64c = 512 float4, 2 per thread
    #pragma unroll
    for (int rep = 0; rep < 2; rep++) {
        int xl  = tid >> 3;              // 0..31
        int c   = rep * 32 + (tid & 7) * 4;
        const float* src = &g_bev[((size_t)by * NXXC + x0 + xl) * CTC + c];
        float4 v = *reinterpret_cast<const float4*>(src);
        t[c + 0][xl] = v.x;
        t[c + 1][xl] = v.y;
        t[c + 2][xl] = v.z;
        t[c + 3][xl] = v.w;
    }
    __syncthreads();
    // store: 64 c-rows of 32 x = 512 float4, 2 per thread
    #pragma unroll
    for (int rep = 0; rep < 2; rep++) {
        int cl = rep * 32 + (tid >> 3);  // 0..63
        int xg = (tid & 7) * 4;
        float4 w;
        w.x = t[cl][xg + 0];
        w.y = t[cl][xg + 1];
        w.z = t[cl][xg + 2];
        w.w = t[cl][xg + 3];
        *reinterpret_cast<float4*>(
            &out[(((size_t)(b * CTC + cl) * NYYC) + y) * NXXC + x0 + xg]) = w;
    }
}

// ---------------- launch ----------------
extern "C" void kernel_launch(void* const* d_in, const int* in_sizes, int n_in,
                              void* d_out, int out_size)
{
    const float* x          = (const float*)d_in[0];
    const float* rots       = (const float*)d_in[1];
    const float* trans      = (const float*)d_in[2];
    const float* intrins    = (const float*)d_in[3];
    const float* post_rots  = (const float*)d_in[4];
    const float* post_trans = (const float*)d_in[5];
    const float* Wd         = (const float*)d_in[6];
    const float* bd         = (const float*)d_in[7];
    float* out = (float*)d_out;

    cudaFuncSetAttribute(k_gemm, cudaFuncAttributeMaxDynamicSharedMemorySize, GEMM_SMEM);

    k_prep<<<1281, 256>>>(Wd, bd, rots, trans, intrins, post_rots, post_trans);
    k_gemm<<<NIMG * 11, 128, GEMM_SMEM>>>(x);
    k_col<<<NCOL, 256>>>();
    k_transpose<<<dim3(4, BB * NYYC), 256>>>(out);
}